// round 3
// baseline (speedup 1.0000x reference)
#include <cuda_runtime.h>
#include <math.h>

#define NN 8192
#define INF_ 128
#define OUTF 64
#define ALPHA 0.2f

typedef unsigned long long u64;

// ---------------- scratch (allocation-free: __device__ globals) ----------------
__device__ float g_Wh[NN * OUTF];   // projected features, fp32
__device__ float g_f1[NN];          // Wh @ a[:64]
__device__ float g_f2[NN];          // Wh @ a[64:]

// ---------------- kernel 1: Wh = h @ W, f1 = Wh@a_lo, f2 = Wh@a_hi -------------
#define K1_ROWS 16
#define K1_THREADS 128
#define SH_STRIDE (INF_ + 2)   // pad to kill 2-way bank conflict

__global__ void __launch_bounds__(K1_THREADS)
k1_proj(const float* __restrict__ h, const float* __restrict__ W,
        const float* __restrict__ a) {
    __shared__ float sW[INF_ * OUTF];            // 32 KB
    __shared__ float sh[K1_ROWS * SH_STRIDE];    // ~8 KB
    const int tid  = threadIdx.x;
    const int row0 = blockIdx.x * K1_ROWS;

    // load W (contiguous)
    {
        const float4* src = (const float4*)W;
        float4* dst = (float4*)sW;
        #pragma unroll
        for (int i = 0; i < (INF_ * OUTF / 4) / K1_THREADS; i++)
            dst[tid + i * K1_THREADS] = src[tid + i * K1_THREADS];
    }
    // load 16 h rows (padded smem)
    for (int i = tid; i < K1_ROWS * INF_; i += K1_THREADS) {
        int r = i / INF_, c = i % INF_;
        sh[r * SH_STRIDE + c] = h[(size_t)(row0 + r) * INF_ + c];
    }
    __syncthreads();

    const int fg = tid & 15;    // 16 groups * 4 features
    const int rg = tid >> 4;    // 8 groups  * 2 rows
    const int f0 = fg * 4;
    const int r0 = rg * 2;

    float acc[2][4] = {};
    #pragma unroll 16
    for (int k = 0; k < INF_; k++) {
        float4 b = *(const float4*)&sW[k * OUTF + f0];
        float x0 = sh[r0 * SH_STRIDE + k];
        float x1 = sh[(r0 + 1) * SH_STRIDE + k];
        acc[0][0] += x0 * b.x; acc[0][1] += x0 * b.y;
        acc[0][2] += x0 * b.z; acc[0][3] += x0 * b.w;
        acc[1][0] += x1 * b.x; acc[1][1] += x1 * b.y;
        acc[1][2] += x1 * b.z; acc[1][3] += x1 * b.w;
    }

    float a1[4], a2[4];
    #pragma unroll
    for (int c = 0; c < 4; c++) { a1[c] = a[f0 + c]; a2[c] = a[OUTF + f0 + c]; }

    #pragma unroll
    for (int rr = 0; rr < 2; rr++) {
        int row = row0 + r0 + rr;
        *(float4*)&g_Wh[(size_t)row * OUTF + f0] =
            make_float4(acc[rr][0], acc[rr][1], acc[rr][2], acc[rr][3]);
        float p1 = acc[rr][0]*a1[0] + acc[rr][1]*a1[1] + acc[rr][2]*a1[2] + acc[rr][3]*a1[3];
        float p2 = acc[rr][0]*a2[0] + acc[rr][1]*a2[1] + acc[rr][2]*a2[2] + acc[rr][3]*a2[3];
        #pragma unroll
        for (int off = 8; off >= 1; off >>= 1) {
            p1 += __shfl_down_sync(0xffffffffu, p1, off, 16);
            p2 += __shfl_down_sync(0xffffffffu, p2, off, 16);
        }
        if (fg == 0) { g_f1[row] = p1; g_f2[row] = p2; }
    }
}

// ---------------- kernel 2: fused mask + exp + aggregate + normalize + elu -----
// Per block: 64 rows, loop over all j in tiles of 32.
// w_ij = adj ? exp(leakyrelu(f1_i + f2_j)) : 0   (no max-sub needed, see theory)
// out_i = elu( (sum_j w_ij * Wh_j) / (sum_j w_ij) )
#define RROWS 64
#define TJ 32
#define K2_THREADS 256
#define W_STRIDE 33   // u64 stride, pad for bank-conflict-free row access

__device__ __forceinline__ void fma2(u64& acc, u64 a, u64 b) {
    // packed fp32x2 FMA (Blackwell): 2 FMAs per instruction
    asm("fma.rn.f32x2 %0, %1, %2, %0;" : "+l"(acc) : "l"(a), "l"(b));
}

__global__ void __launch_bounds__(K2_THREADS)
k2_gat(const int* __restrict__ adj, float* __restrict__ out) {
    __shared__ u64   sW2[RROWS * W_STRIDE];  // duplicated (w,w) pairs, [r][j]
    __shared__ float sWh[TJ * OUTF];         // Wh tile, [j][f]
    __shared__ float sDen[RROWS];
    __shared__ float sF1[RROWS];

    const int tid  = threadIdx.x;
    const int row0 = blockIdx.x * RROWS;

    if (tid < RROWS) { sF1[tid] = g_f1[row0 + tid]; sDen[tid] = 0.f; }

    // phase-A mapping: one j-column per thread (coalesced adj), 8 rows each
    const int jl  = tid & 31;
    const int rg8 = tid >> 5;          // 8 groups * 8 rows
    // phase-B mapping: 4 rows x 4 feats per thread
    const int fg  = tid & 15;          // 16 groups * 4 feats
    const int rgB = tid >> 4;          // 16 groups * 4 rows
    const int f0  = fg * 4;
    const int rB0 = rgB * 4;
    // den-reduce mapping
    const int rD = tid >> 2;
    const int qD = tid & 3;

    u64 acc[4][2] = {};  // [row][feat-pair]; pair0=(f0,f0+1), pair1=(f0+2,f0+3)

    __syncthreads();

    for (int jt = 0; jt < NN / TJ; jt++) {
        const int j0 = jt * TJ;

        // ---- load Wh tile: 2048 floats = 512 float4 ----
        {
            const float4* src = (const float4*)&g_Wh[(size_t)j0 * OUTF];
            float4* dst = (float4*)sWh;
            dst[tid] = src[tid];
            dst[tid + 256] = src[tid + 256];
        }
        // ---- phase A: masked exp weights ----
        {
            const float f2j = g_f2[j0 + jl];
            const int* arow = adj + (size_t)(row0 + rg8 * 8) * NN + j0 + jl;
            #pragma unroll
            for (int k = 0; k < 8; k++) {
                int   av = arow[(size_t)k * NN];
                int   r  = rg8 * 8 + k;
                float x  = sF1[r] + f2j;
                float e  = fmaxf(x, ALPHA * x);          // leaky relu (ALPHA<1)
                float w  = (av > 0) ? __expf(e) : 0.f;
                unsigned wb = __float_as_uint(w);
                sW2[r * W_STRIDE + jl] = ((u64)wb << 32) | (u64)wb;  // (w,w)
            }
        }
        __syncthreads();

        // ---- denominator partial (row sums of w) ----
        {
            const float* wf = (const float*)sW2;   // low half of each u64 = w
            float s = 0.f;
            #pragma unroll
            for (int j = 0; j < 8; j++)
                s += wf[(rD * W_STRIDE + qD * 8 + j) * 2];
            s += __shfl_down_sync(0xffffffffu, s, 2);
            s += __shfl_down_sync(0xffffffffu, s, 1);
            if (qD == 0) sDen[rD] += s;            // single writer per row
        }

        // ---- phase B: acc += w * Wh ----
        #pragma unroll
        for (int j = 0; j < TJ; j++) {
            const u64* bb = (const u64*)&sWh[j * OUTF + f0];
            u64 b0 = bb[0], b1 = bb[1];
            #pragma unroll
            for (int rr = 0; rr < 4; rr++) {
                u64 w = sW2[(rB0 + rr) * W_STRIDE + j];
                fma2(acc[rr][0], w, b0);
                fma2(acc[rr][1], w, b1);
            }
        }
        __syncthreads();  // protect sW2/sWh reuse next tile
    }

    // ---- epilogue: divide + elu + store ----
    #pragma unroll
    for (int rr = 0; rr < 4; rr++) {
        int r = rB0 + rr;
        float inv = 1.f / sDen[r];
        float v[4];
        v[0] = __uint_as_float((unsigned)(acc[rr][0]      )) * inv;
        v[1] = __uint_as_float((unsigned)(acc[rr][0] >> 32)) * inv;
        v[2] = __uint_as_float((unsigned)(acc[rr][1]      )) * inv;
        v[3] = __uint_as_float((unsigned)(acc[rr][1] >> 32)) * inv;
        #pragma unroll
        for (int c = 0; c < 4; c++)
            v[c] = (v[c] > 0.f) ? v[c] : expm1f(v[c]);   // elu (alpha=1)
        *(float4*)&out[(size_t)(row0 + r) * OUTF + f0] =
            make_float4(v[0], v[1], v[2], v[3]);
    }
}

// ---------------- launcher -----------------------------------------------------
extern "C" void kernel_launch(void* const* d_in, const int* in_sizes, int n_in,
                              void* d_out, int out_size) {
    // resolve inputs by element count (robust to ordering):
    // h: 8192*128 = 1048576, adj: 8192*8192 = 67108864, W: 128*64 = 8192, a: 128
    const float* h = nullptr; const int* adj = nullptr;
    const float* W = nullptr; const float* a = nullptr;
    for (int i = 0; i < n_in; i++) {
        switch (in_sizes[i]) {
            case 1048576:  h   = (const float*)d_in[i]; break;
            case 67108864: adj = (const int*)  d_in[i]; break;
            case 8192:     W   = (const float*)d_in[i]; break;
            case 128:      a   = (const float*)d_in[i]; break;
            default: break;
        }
    }
    float* out = (float*)d_out;

    k1_proj<<<NN / K1_ROWS, K1_THREADS>>>(h, W, a);
    k2_gat<<<NN / RROWS, K2_THREADS>>>(adj, out);
    (void)out_size;
}

// round 6
// speedup vs baseline: 6.7673x; 6.7673x over previous
#include <cuda_runtime.h>
#include <math.h>
#include <stdint.h>

#define NN 8192
#define INF_ 128
#define OUTF 64

typedef unsigned int u32;

#define JSPLIT 4
#define JPC (NN / JSPLIT)        // 2048 j per CTA
#define RB 256                   // rows per CTA
#define NK (JPC / 8)             // 256 k-steps of 8 j
#define K2T 256

// ---------------- scratch (__device__ globals; no allocation) ------------------
__device__ float g_WhT[72 * NN];            // [n][j]; 0..63 = WhT (tf32), 64 = ones, 65..71 = 0
__device__ float g_E1[NN], g_F1[NN];        // exp(f1), exp(0.2 f1)
__device__ float g_E2[NN], g_F2[NN];        // exp(f2), exp(0.2 f2)
__device__ float g_part[JSPLIT * NN * OUTF];// numerator partials
__device__ float g_denp[JSPLIT * NN];       // denominator partials

// ---------------- helpers -------------------------------------------------------
__device__ __forceinline__ float tf32r(float x) {
    u32 r; asm("cvt.rna.tf32.f32 %0, %1;" : "=r"(r) : "f"(x));
    return __uint_as_float(r);
}

// m16n8k8 tf32 MMA (row.col): A 4 regs, B 2 regs, C/D 4 f32.
// thread (g=lane>>2, c=lane&3): a0=A[g][c], a1=A[g+8][c], a2=A[g][c+4], a3=A[g+8][c+4]
//                               b0=B[c][g], b1=B[c+4][g]
//                               d0=D[g][2c], d1=D[g][2c+1], d2=D[g+8][2c], d3=D[g+8][2c+1]
__device__ __forceinline__ void mma_k8(float* d, u32 a0, u32 a1, u32 a2, u32 a3,
                                       u32 b0, u32 b1) {
    asm volatile(
        "mma.sync.aligned.m16n8k8.row.col.f32.tf32.tf32.f32 "
        "{%0,%1,%2,%3}, {%4,%5,%6,%7}, {%8,%9}, {%0,%1,%2,%3};"
        : "+f"(d[0]), "+f"(d[1]), "+f"(d[2]), "+f"(d[3])
        : "r"(a0), "r"(a1), "r"(a2), "r"(a3), "r"(b0), "r"(b1));
}

// ---------------- kernel 1: Wh = h @ W -> g_WhT (tf32), E/F factors ------------
#define K1_ROWS 16
#define K1_THREADS 128
#define SH_STRIDE (INF_ + 2)

__global__ void __launch_bounds__(K1_THREADS)
k1_proj(const float* __restrict__ h, const float* __restrict__ W,
        const float* __restrict__ a) {
    __shared__ float sW[INF_ * OUTF];
    __shared__ float sh[K1_ROWS * SH_STRIDE];
    const int tid  = threadIdx.x;
    const int row0 = blockIdx.x * K1_ROWS;

    {
        const float4* src = (const float4*)W;
        float4* dst = (float4*)sW;
        #pragma unroll
        for (int i = 0; i < (INF_ * OUTF / 4) / K1_THREADS; i++)
            dst[tid + i * K1_THREADS] = src[tid + i * K1_THREADS];
    }
    for (int i = tid; i < K1_ROWS * INF_; i += K1_THREADS) {
        int r = i / INF_, c = i % INF_;
        sh[r * SH_STRIDE + c] = h[(size_t)(row0 + r) * INF_ + c];
    }
    __syncthreads();

    const int fg = tid & 15;
    const int rg = tid >> 4;
    const int f0 = fg * 4;
    const int r0 = rg * 2;

    float acc[2][4] = {};
    #pragma unroll 16
    for (int k = 0; k < INF_; k++) {
        float4 b = *(const float4*)&sW[k * OUTF + f0];
        float x0 = sh[r0 * SH_STRIDE + k];
        float x1 = sh[(r0 + 1) * SH_STRIDE + k];
        acc[0][0] += x0 * b.x; acc[0][1] += x0 * b.y;
        acc[0][2] += x0 * b.z; acc[0][3] += x0 * b.w;
        acc[1][0] += x1 * b.x; acc[1][1] += x1 * b.y;
        acc[1][2] += x1 * b.z; acc[1][3] += x1 * b.w;
    }

    float a1[4], a2[4];
    #pragma unroll
    for (int c = 0; c < 4; c++) { a1[c] = a[f0 + c]; a2[c] = a[OUTF + f0 + c]; }

    #pragma unroll
    for (int rr = 0; rr < 2; rr++) {
        int row = row0 + r0 + rr;
        #pragma unroll
        for (int c = 0; c < 4; c++)
            g_WhT[(size_t)(f0 + c) * NN + row] = tf32r(acc[rr][c]);
        float p1 = acc[rr][0]*a1[0] + acc[rr][1]*a1[1] + acc[rr][2]*a1[2] + acc[rr][3]*a1[3];
        float p2 = acc[rr][0]*a2[0] + acc[rr][1]*a2[1] + acc[rr][2]*a2[2] + acc[rr][3]*a2[3];
        #pragma unroll
        for (int off = 8; off >= 1; off >>= 1) {
            p1 += __shfl_down_sync(0xffffffffu, p1, off, 16);
            p2 += __shfl_down_sync(0xffffffffu, p2, off, 16);
        }
        if (fg == 0) {
            g_E1[row] = expf(p1);  g_F1[row] = expf(0.2f * p1);
            g_E2[row] = expf(p2);  g_F2[row] = expf(0.2f * p2);
        }
    }
    // constant rows 64..71 (ones column for denominator, zero padding)
    if (tid < 128) {
        int f = 64 + (tid >> 4);
        int r = row0 + (tid & 15);
        g_WhT[(size_t)f * NN + r] = (f == 64) ? 1.0f : 0.0f;
    }
}

// ---------------- kernel 2: fused mask+weight-gen + tensor-core aggregate ------
// Per CTA: 256 rows x 2048 j. 8 warps, each m32 x n72 (n-col 64 = denominator).
#define SBS 72                    // float stride per B row (72 mod 32 = 8: conflict-free)
#define SBF (72 * SBS)            // 5184 floats per buffer
#define SMEM_K2 ((2 * SBF + (JPC / 2) * 4) * 4)   // 57856 bytes

__global__ void __launch_bounds__(K2T, 1)
k2_gat(const int* __restrict__ adj) {
    extern __shared__ float sm[];
    float*  sBbuf0 = sm;
    float*  sBbuf1 = sm + SBF;
    float4* sEF    = (float4*)(sm + 2 * SBF);  // (E2[2i],E2[2i+1],F2[2i],F2[2i+1])

    const int tid  = threadIdx.x;
    const int wid  = tid >> 5;
    const int lane = tid & 31;
    const int g    = lane >> 2;
    const int c    = lane & 3;
    const int rb   = blockIdx.x & 31;
    const int js   = blockIdx.x >> 5;
    const int row0 = rb * RB;
    const int jbase = js * JPC;
    const int r0w  = row0 + wid * 32;

    // ---- stage sEF for the whole CTA j-range ----
    for (int i = tid; i < JPC / 2; i += K2T) {
        float2 e2 = *(const float2*)&g_E2[jbase + 2 * i];
        float2 f2 = *(const float2*)&g_F2[jbase + 2 * i];
        sEF[i] = make_float4(e2.x, e2.y, f2.x, f2.y);
    }
    // ---- stage B chunk 0 ----
    #pragma unroll
    for (int q = 0; q < 5; q++) {
        int slot = tid + q * K2T;
        if (slot < 1152) {
            int n = slot >> 4, p = slot & 15;
            float4 v = *(const float4*)&g_WhT[(size_t)n * NN + jbase + p * 4];
            *(float4*)&sBbuf0[n * SBS + p * 4] = v;
        }
    }
    // ---- per-lane row factors ----
    float e1r[4], f1r[4];
    #pragma unroll
    for (int rr = 0; rr < 4; rr++) {
        int row = r0w + rr * 8 + g;
        e1r[rr] = g_E1[row];
        f1r[rr] = g_F1[row];
    }
    // ---- adj prefetch prologue (depth 4): av[slot][rr] covers j = t*8 + 2c,2c+1 ----
    uint2 av[4][4];
    #pragma unroll
    for (int t = 0; t < 4; t++)
        #pragma unroll
        for (int rr = 0; rr < 4; rr++)
            av[t][rr] = *(const uint2*)(adj + (size_t)(r0w + rr * 8 + g) * NN
                                            + jbase + t * 8 + 2 * c);

    float acc[2][9][4];
    #pragma unroll
    for (int mt = 0; mt < 2; mt++)
        #pragma unroll
        for (int nt = 0; nt < 9; nt++)
            #pragma unroll
            for (int q = 0; q < 4; q++) acc[mt][nt][q] = 0.f;

    __syncthreads();

    for (int ch = 0; ch < 32; ch++) {
        const float* sb  = (ch & 1) ? sBbuf1 : sBbuf0;
        float*       sbn = (ch & 1) ? sBbuf0 : sBbuf1;
        float4 stg[5];
        const bool do_stage = (ch < 31);
        if (do_stage) {
            #pragma unroll
            for (int q = 0; q < 5; q++) {
                int slot = tid + q * K2T;
                if (slot < 1152) {
                    int n = slot >> 4, p = slot & 15;
                    stg[q] = *(const float4*)&g_WhT[(size_t)n * NN + jbase
                                                    + (ch + 1) * 64 + p * 4];
                }
            }
        }
        #pragma unroll
        for (int k8 = 0; k8 < 8; k8++) {
            const int t  = ch * 8 + k8;
            const int sl = k8 & 3;
            uint2 a4[4];
            #pragma unroll
            for (int rr = 0; rr < 4; rr++) a4[rr] = av[sl][rr];
            if (t + 4 < NK) {
                #pragma unroll
                for (int rr = 0; rr < 4; rr++)
                    av[sl][rr] = *(const uint2*)(adj + (size_t)(r0w + rr * 8 + g) * NN
                                                     + jbase + (t + 4) * 8 + 2 * c);
            }
            float4 ef = sEF[t * 4 + c];   // E2/F2 at j = t*8+2c, +1 (broadcast across g)
            // weights: w = max(E1*E2, F1*F2); tf32-truncate + adj-mask in one LOP3
            u32 aw[4][2];
            #pragma unroll
            for (int rr = 0; rr < 4; rr++) {
                float wl = fmaxf(e1r[rr] * ef.x, f1r[rr] * ef.z);
                float wh = fmaxf(e1r[rr] * ef.y, f1r[rr] * ef.w);
                aw[rr][0] = __float_as_uint(wl) & 0xFFFFE000u & (u32)(-(int)a4[rr].x);
                aw[rr][1] = __float_as_uint(wh) & 0xFFFFE000u & (u32)(-(int)a4[rr].y);
            }
            // k-index mapping: k=c <-> j=t*8+2c (aw[.][0], b.x); k=c+4 <-> j=t*8+2c+1
            #pragma unroll
            for (int nt = 0; nt < 9; nt++) {
                float2 b = *(const float2*)&sb[(nt * 8 + g) * SBS + k8 * 8 + 2 * c];
                u32 b0 = __float_as_uint(b.x);
                u32 b1 = __float_as_uint(b.y);
                mma_k8(acc[0][nt], aw[0][0], aw[1][0], aw[0][1], aw[1][1], b0, b1);
                mma_k8(acc[1][nt], aw[2][0], aw[3][0], aw[2][1], aw[3][1], b0, b1);
            }
        }
        if (do_stage) {
            #pragma unroll
            for (int q = 0; q < 5; q++) {
                int slot = tid + q * K2T;
                if (slot < 1152) {
                    int n = slot >> 4, p = slot & 15;
                    *(float4*)&sbn[n * SBS + p * 4] = stg[q];
                }
            }
        }
        __syncthreads();
    }

    // ---- epilogue: write partials ----
    #pragma unroll
    for (int mt = 0; mt < 2; mt++) {
        int ra = r0w + mt * 16 + g;
        int rc = ra + 8;
        #pragma unroll
        for (int nt = 0; nt < 8; nt++) {
            int col = nt * 8 + 2 * c;
            *(float2*)&g_part[((size_t)js * NN + ra) * OUTF + col] =
                make_float2(acc[mt][nt][0], acc[mt][nt][1]);
            *(float2*)&g_part[((size_t)js * NN + rc) * OUTF + col] =
                make_float2(acc[mt][nt][2], acc[mt][nt][3]);
        }
        if (c == 0) {                         // n-col 64 (ones) = denominator
            g_denp[js * NN + ra] = acc[mt][8][0];
            g_denp[js * NN + rc] = acc[mt][8][2];
        }
    }
}

// ---------------- kernel 3: reduce partials, normalize, elu --------------------
__global__ void __launch_bounds__(256)
k3_final(float* __restrict__ out) {
    int idx = blockIdx.x * 256 + threadIdx.x;   // 0 .. NN*OUTF-1
    int row = idx >> 6;
    float num = 0.f, den = 0.f;
    #pragma unroll
    for (int s = 0; s < JSPLIT; s++) {
        num += g_part[(size_t)s * NN * OUTF + idx];
        den += g_denp[s * NN + row];
    }
    float v = num / den;
    out[idx] = (v > 0.f) ? v : expm1f(v);
}

// ---------------- launcher -----------------------------------------------------
extern "C" void kernel_launch(void* const* d_in, const int* in_sizes, int n_in,
                              void* d_out, int out_size) {
    const float* h = nullptr; const int* adj = nullptr;
    const float* W = nullptr; const float* a = nullptr;
    for (int i = 0; i < n_in; i++) {
        switch (in_sizes[i]) {
            case 1048576:  h   = (const float*)d_in[i]; break;
            case 67108864: adj = (const int*)  d_in[i]; break;
            case 8192:     W   = (const float*)d_in[i]; break;
            case 128:      a   = (const float*)d_in[i]; break;
            default: break;
        }
    }
    float* out = (float*)d_out;

    cudaFuncSetAttribute(k2_gat, cudaFuncAttributeMaxDynamicSharedMemorySize, SMEM_K2);

    k1_proj<<<NN / K1_ROWS, K1_THREADS>>>(h, W, a);
    k2_gat<<<32 * JSPLIT, K2T, SMEM_K2>>>(adj);
    k3_final<<<(NN * OUTF) / 256, 256>>>(out);
    (void)out_size;
}

// round 7
// speedup vs baseline: 8.0057x; 1.1830x over previous
#include <cuda_runtime.h>
#include <cuda_fp16.h>
#include <math.h>
#include <stdint.h>

#define NN 8192
#define INF_ 128
#define OUTF 64

typedef unsigned int u32;

#define JSPLIT 4
#define JPC (NN / JSPLIT)        // 2048 j per CTA
#define RB 256                   // rows per CTA
#define NK16 (JPC / 16)          // 128 k16-steps
#define K2T 256

// ---------------- scratch (__device__ globals; no allocation) ------------------
__device__ __half g_WhH[72 * NN];           // [n][j] fp16; 0..63 = WhT, 64 = ones, 65..71 = 0
__device__ float g_E1[NN], g_F1[NN];        // exp(f1), exp(0.2 f1)   (unscaled)
__device__ float g_E2[NN], g_F2[NN];        // exp(f2), exp(0.2 f2)
__device__ int   g_ME2i, g_MF2i;            // global max of E2 / F2 (float bits, positive)
__device__ float g_part[JSPLIT * NN * OUTF];// numerator partials
__device__ float g_denp[JSPLIT * NN];       // denominator partials

// ---------------- helpers -------------------------------------------------------
__device__ __forceinline__ u32 packh2(float hi, float lo) {
    u32 d; asm("cvt.rn.f16x2.f32 %0, %1, %2;" : "=r"(d) : "f"(hi), "f"(lo));
    return d;
}
__device__ __forceinline__ u32 pairmask(uint2 a) {   // adj in {0,1}
    u32 nx = (u32)(-(int)a.x);
    u32 ny = (u32)(-(int)a.y);
    return (nx & 0xFFFFu) | (ny & 0xFFFF0000u);
}
// m16n8k16 fp16 MMA (row.col), f32 accum.
__device__ __forceinline__ void mma_f16(float* d, u32 a0, u32 a1, u32 a2, u32 a3,
                                        u32 b0, u32 b1) {
    asm volatile(
        "mma.sync.aligned.m16n8k16.row.col.f32.f16.f16.f32 "
        "{%0,%1,%2,%3}, {%4,%5,%6,%7}, {%8,%9}, {%0,%1,%2,%3};"
        : "+f"(d[0]), "+f"(d[1]), "+f"(d[2]), "+f"(d[3])
        : "r"(a0), "r"(a1), "r"(a2), "r"(a3), "r"(b0), "r"(b1));
}

// ---------------- kernel 1: Wh = h @ W -> g_WhH (fp16), E/F factors, maxes -----
#define K1_ROWS 64
#define K1T 256
#define SH 132                          // h row stride (mult of 4; mod-32 = 4)
#define K1_SMEM ((INF_ * OUTF + K1_ROWS * SH) * 4)   // 66560 bytes

__global__ void __launch_bounds__(K1T)
k1_proj(const float* __restrict__ h, const float* __restrict__ W,
        const float* __restrict__ a) {
    extern __shared__ float smk1[];
    float* sW = smk1;                   // [128][64]
    float* sh = smk1 + INF_ * OUTF;     // [64][SH]
    __shared__ float redA[16], redB[16];

    const int tid  = threadIdx.x;
    const int row0 = blockIdx.x * K1_ROWS;

    #pragma unroll
    for (int q = 0; q < 8; q++)         // W: 2048 float4
        ((float4*)sW)[tid + q * K1T] = ((const float4*)W)[tid + q * K1T];
    #pragma unroll
    for (int q = 0; q < 8; q++) {       // h: 2048 float4
        int slot = tid + q * K1T;
        int r = slot >> 5, cq = slot & 31;
        *(float4*)&sh[r * SH + cq * 4] =
            *(const float4*)&h[(size_t)(row0 + r) * INF_ + cq * 4];
    }
    __syncthreads();

    const int fg = tid & 15;            // 16 col groups * 4
    const int rg = tid >> 4;            // 16 row groups * 4
    const int f0 = fg * 4;
    const int r0 = rg * 4;

    float acc[4][4] = {};
    #pragma unroll 16
    for (int k = 0; k < INF_; k++) {
        float4 b = *(const float4*)&sW[k * OUTF + f0];
        #pragma unroll
        for (int rr = 0; rr < 4; rr++) {
            float x = sh[(r0 + rr) * SH + k];
            acc[rr][0] += x * b.x; acc[rr][1] += x * b.y;
            acc[rr][2] += x * b.z; acc[rr][3] += x * b.w;
        }
    }

    // store Wh as fp16, transposed: g_WhH[f][row], 4 rows packed per store
    #pragma unroll
    for (int cc = 0; cc < 4; cc++) {
        __half2 lo = __floats2half2_rn(acc[0][cc], acc[1][cc]);
        __half2 hi = __floats2half2_rn(acc[2][cc], acc[3][cc]);
        uint2 v = make_uint2(*(u32*)&lo, *(u32*)&hi);
        *(uint2*)&g_WhH[(size_t)(f0 + cc) * NN + row0 + r0] = v;
    }

    // f1/f2 per row, then E/F factors
    float a1[4], a2[4];
    #pragma unroll
    for (int c = 0; c < 4; c++) { a1[c] = a[f0 + c]; a2[c] = a[OUTF + f0 + c]; }

    float locE2 = 0.f, locF2 = 0.f;
    #pragma unroll
    for (int rr = 0; rr < 4; rr++) {
        float p1 = acc[rr][0]*a1[0] + acc[rr][1]*a1[1] + acc[rr][2]*a1[2] + acc[rr][3]*a1[3];
        float p2 = acc[rr][0]*a2[0] + acc[rr][1]*a2[1] + acc[rr][2]*a2[2] + acc[rr][3]*a2[3];
        #pragma unroll
        for (int off = 8; off >= 1; off >>= 1) {
            p1 += __shfl_down_sync(0xffffffffu, p1, off, 16);
            p2 += __shfl_down_sync(0xffffffffu, p2, off, 16);
        }
        if (fg == 0) {
            int row = row0 + r0 + rr;
            float e1 = expf(p1), fl1 = expf(0.2f * p1);
            float e2 = expf(p2), fl2 = expf(0.2f * p2);
            g_E1[row] = e1;  g_F1[row] = fl1;
            g_E2[row] = e2;  g_F2[row] = fl2;
            locE2 = fmaxf(locE2, e2); locF2 = fmaxf(locF2, fl2);
        }
    }
    if (fg == 0) { redA[rg] = locE2; redB[rg] = locF2; }

    // constant rows 64..71 (ones column for denominator, zero padding)
    for (int i = tid; i < 8 * K1_ROWS; i += K1T) {
        int f = 64 + (i >> 6);
        int r = row0 + (i & 63);
        g_WhH[(size_t)f * NN + r] = (f == 64) ? __float2half(1.0f) : __float2half(0.0f);
    }
    __syncthreads();
    if (tid == 0) {
        float mA = 0.f, mB = 0.f;
        #pragma unroll
        for (int i = 0; i < 16; i++) { mA = fmaxf(mA, redA[i]); mB = fmaxf(mB, redB[i]); }
        atomicMax(&g_ME2i, __float_as_int(mA));
        atomicMax(&g_MF2i, __float_as_int(mB));
    }
}

// ---------------- kernel 2: fused mask+weight-gen + fp16 tensor aggregate ------
// Per CTA: 256 rows x 2048 j. 8 warps, each m32 x n72 (n-col 64 = denominator).
#define SBH 72                           // halves stride per B n-row (144 B)
#define SB_BYTES (72 * SBH * 2)          // 10368 B per buffer
#define SMEM_K2 (16384 + 2 * SB_BYTES)   // sEF + 2 B buffers = 37120 B

__global__ void __launch_bounds__(K2T, 1)
k2_gat(const int* __restrict__ adj) {
    extern __shared__ char smraw[];
    float4* sEF  = (float4*)smraw;                       // [JPC/2] (E2 lo,hi, F2 lo,hi)
    __half* sB0  = (__half*)(smraw + 16384);
    __half* sB1  = (__half*)(smraw + 16384 + SB_BYTES);

    const int tid  = threadIdx.x;
    const int wid  = tid >> 5;
    const int lane = tid & 31;
    const int g    = lane >> 2;
    const int c    = lane & 3;
    const int rb   = blockIdx.x & 31;
    const int js   = blockIdx.x >> 5;
    const int row0 = rb * RB;
    const int jbase = js * JPC;
    const int r0w  = row0 + wid * 32;

    // ---- stage sEF for the whole CTA j-range ----
    for (int i = tid; i < JPC / 2; i += K2T) {
        float2 e2 = *(const float2*)&g_E2[jbase + 2 * i];
        float2 f2 = *(const float2*)&g_F2[jbase + 2 * i];
        sEF[i] = make_float4(e2.x, e2.y, f2.x, f2.y);
    }
    // ---- stage B chunk 0 (72 n x 64 j halves = 576 uint4) ----
    #pragma unroll
    for (int q = 0; q < 3; q++) {
        int slot = tid + q * K2T;
        if (slot < 576) {
            int n = slot >> 3, p = slot & 7;
            uint4 v = *(const uint4*)&g_WhH[(size_t)n * NN + jbase + p * 8];
            *(uint4*)((char*)sB0 + n * 144 + p * 16) = v;
        }
    }
    // ---- per-lane row factors, rescaled so weights <= 1 (softmax-invariant) ----
    const float ME2 = __int_as_float(g_ME2i);
    const float MF2 = __int_as_float(g_MF2i);
    float e1r[4], f1r[4];
    #pragma unroll
    for (int rr = 0; rr < 4; rr++) {
        int row = r0w + rr * 8 + g;
        float e1 = g_E1[row], f1 = g_F1[row];
        float inv = 1.0f / fmaxf(e1 * ME2, f1 * MF2);
        e1r[rr] = e1 * inv;
        f1r[rr] = f1 * inv;
    }
    // ---- adj base pointers + prefetch prologue (depth 2 k16-steps) ----
    const int* ap[4];
    #pragma unroll
    for (int rr = 0; rr < 4; rr++)
        ap[rr] = adj + (size_t)(r0w + rr * 8 + g) * NN + jbase + 2 * c;
    uint2 av[2][4][2];
    #pragma unroll
    for (int t = 0; t < 2; t++)
        #pragma unroll
        for (int rr = 0; rr < 4; rr++) {
            av[t][rr][0] = *(const uint2*)(ap[rr] + t * 16);
            av[t][rr][1] = *(const uint2*)(ap[rr] + t * 16 + 8);
        }

    float acc[2][9][4];
    #pragma unroll
    for (int mt = 0; mt < 2; mt++)
        #pragma unroll
        for (int nt = 0; nt < 9; nt++)
            #pragma unroll
            for (int q = 0; q < 4; q++) acc[mt][nt][q] = 0.f;

    __syncthreads();

    for (int ch = 0; ch < 32; ch++) {
        const __half* sb  = (ch & 1) ? sB1 : sB0;
        __half*       sbn = (ch & 1) ? sB0 : sB1;
        uint4 stg[3];
        const bool do_stage = (ch < 31);
        if (do_stage) {
            #pragma unroll
            for (int q = 0; q < 3; q++) {
                int slot = tid + q * K2T;
                if (slot < 576) {
                    int n = slot >> 3, p = slot & 7;
                    stg[q] = *(const uint4*)&g_WhH[(size_t)n * NN + jbase
                                                   + (ch + 1) * 64 + p * 8];
                }
            }
        }
        #pragma unroll
        for (int k16 = 0; k16 < 4; k16++) {
            const int t  = ch * 4 + k16;
            const int sl = t & 1;
            uint2 alo[4], ahi[4];
            #pragma unroll
            for (int rr = 0; rr < 4; rr++) { alo[rr] = av[sl][rr][0]; ahi[rr] = av[sl][rr][1]; }
            if (t + 2 < NK16) {
                #pragma unroll
                for (int rr = 0; rr < 4; rr++) {
                    av[sl][rr][0] = *(const uint2*)(ap[rr] + (t + 2) * 16);
                    av[sl][rr][1] = *(const uint2*)(ap[rr] + (t + 2) * 16 + 8);
                }
            }
            float4 efl = sEF[t * 8 + c];        // j = t*16 + 2c, +1
            float4 efh = sEF[t * 8 + c + 4];    // j = t*16 + 2c+8, +9
            u32 aA[4][2];
            #pragma unroll
            for (int rr = 0; rr < 4; rr++) {
                float wl0 = fmaxf(e1r[rr] * efl.x, f1r[rr] * efl.z);
                float wl1 = fmaxf(e1r[rr] * efl.y, f1r[rr] * efl.w);
                float wh0 = fmaxf(e1r[rr] * efh.x, f1r[rr] * efh.z);
                float wh1 = fmaxf(e1r[rr] * efh.y, f1r[rr] * efh.w);
                aA[rr][0] = packh2(wl1, wl0) & pairmask(alo[rr]);
                aA[rr][1] = packh2(wh1, wh0) & pairmask(ahi[rr]);
            }
            #pragma unroll
            for (int nt = 0; nt < 9; nt++) {
                const __half* bp = &sb[(nt * 8 + g) * SBH + k16 * 16 + 2 * c];
                u32 b0 = *(const u32*)bp;
                u32 b1 = *(const u32*)(bp + 8);
                mma_f16(acc[0][nt], aA[0][0], aA[1][0], aA[0][1], aA[1][1], b0, b1);
                mma_f16(acc[1][nt], aA[2][0], aA[3][0], aA[2][1], aA[3][1], b0, b1);
            }
        }
        if (do_stage) {
            #pragma unroll
            for (int q = 0; q < 3; q++) {
                int slot = tid + q * K2T;
                if (slot < 576) {
                    int n = slot >> 3, p = slot & 7;
                    *(uint4*)((char*)sbn + n * 144 + p * 16) = stg[q];
                }
            }
        }
        __syncthreads();
    }

    // ---- epilogue: write partials (scaling cancels in num/den) ----
    #pragma unroll
    for (int mt = 0; mt < 2; mt++) {
        int ra = r0w + mt * 16 + g;
        int rc = ra + 8;
        #pragma unroll
        for (int nt = 0; nt < 8; nt++) {
            int col = nt * 8 + 2 * c;
            *(float2*)&g_part[((size_t)js * NN + ra) * OUTF + col] =
                make_float2(acc[mt][nt][0], acc[mt][nt][1]);
            *(float2*)&g_part[((size_t)js * NN + rc) * OUTF + col] =
                make_float2(acc[mt][nt][2], acc[mt][nt][3]);
        }
        if (c == 0) {                         // n-col 64 (ones) = denominator
            g_denp[js * NN + ra] = acc[mt][8][0];
            g_denp[js * NN + rc] = acc[mt][8][2];
        }
    }
}

// ---------------- kernel 3: reduce partials, normalize, elu --------------------
__global__ void __launch_bounds__(256)
k3_final(float* __restrict__ out) {
    int idx = blockIdx.x * 256 + threadIdx.x;   // 0 .. NN*OUTF-1
    int row = idx >> 6;
    float num = 0.f, den = 0.f;
    #pragma unroll
    for (int s = 0; s < JSPLIT; s++) {
        num += g_part[(size_t)s * NN * OUTF + idx];
        den += g_denp[s * NN + row];
    }
    float v = num / den;
    out[idx] = (v > 0.f) ? v : expm1f(v);
}

// ---------------- launcher -----------------------------------------------------
extern "C" void kernel_launch(void* const* d_in, const int* in_sizes, int n_in,
                              void* d_out, int out_size) {
    const float* h = nullptr; const int* adj = nullptr;
    const float* W = nullptr; const float* a = nullptr;
    for (int i = 0; i < n_in; i++) {
        switch (in_sizes[i]) {
            case 1048576:  h   = (const float*)d_in[i]; break;
            case 67108864: adj = (const int*)  d_in[i]; break;
            case 8192:     W   = (const float*)d_in[i]; break;
            case 128:      a   = (const float*)d_in[i]; break;
            default: break;
        }
    }
    float* out = (float*)d_out;

    cudaFuncSetAttribute(k1_proj, cudaFuncAttributeMaxDynamicSharedMemorySize, K1_SMEM);

    k1_proj<<<NN / K1_ROWS, K1T, K1_SMEM>>>(h, W, a);
    k2_gat<<<32 * JSPLIT, K2T, SMEM_K2>>>(adj);
    k3_final<<<(NN * OUTF) / 256, 256>>>(out);
    (void)out_size;
}

// round 8
// speedup vs baseline: 9.2076x; 1.1501x over previous
#include <cuda_runtime.h>
#include <cuda_fp16.h>
#include <math.h>
#include <stdint.h>

#define NN 8192
#define INF_ 128
#define OUTF 64

typedef unsigned int u32;

#define JSPLIT 4
#define JPC (NN / JSPLIT)        // 2048 j per CTA
#define RB2 128                  // rows per k2 CTA
#define NK16 (JPC / 16)          // 128 k16-steps
#define K2T 256

// ---------------- scratch (__device__ globals; no allocation) ------------------
__device__ __half g_WhH[72 * NN];           // [n][j] fp16; 0..63 = WhT, 64 = ones, 65..71 = 0
__device__ float g_E1[NN], g_F1[NN];        // exp(f1), exp(0.2 f1)   (unscaled)
__device__ float g_E2[NN], g_F2[NN];        // exp(f2), exp(0.2 f2)
__device__ int   g_ME2i, g_MF2i;            // global max of E2 / F2 (float bits, positive)
__device__ float g_part[JSPLIT * NN * OUTF];// numerator partials
__device__ float g_denp[JSPLIT * NN];       // denominator partials

// ---------------- helpers -------------------------------------------------------
__device__ __forceinline__ u32 packh2(float hi, float lo) {
    u32 d; asm("cvt.rn.f16x2.f32 %0, %1, %2;" : "=r"(d) : "f"(hi), "f"(lo));
    return d;
}
__device__ __forceinline__ u32 pairmask2(u32 ax, u32 ay) {   // adj in {0,1}
    return ((u32)(-(int)ax) & 0xFFFFu) | ((u32)(-(int)ay) << 16);
}
__device__ __forceinline__ u32 smem_u32(const void* p) {
    u32 a;
    asm("{ .reg .u64 t; cvta.to.shared.u64 t, %1; cvt.u32.u64 %0, t; }" : "=r"(a) : "l"(p));
    return a;
}
__device__ __forceinline__ void cpa16(u32 dst, const void* src) {
    asm volatile("cp.async.cg.shared.global [%0], [%1], 16;" :: "r"(dst), "l"(src));
}
__device__ __forceinline__ void cpa_commit() {
    asm volatile("cp.async.commit_group;" ::: "memory");
}
#define CPA_WAIT(n) asm volatile("cp.async.wait_group %0;" :: "n"(n) : "memory")

// m16n8k16 fp16 MMA (row.col), f32 accum.
__device__ __forceinline__ void mma_f16(float* d, u32 a0, u32 a1, u32 a2, u32 a3,
                                        u32 b0, u32 b1) {
    asm volatile(
        "mma.sync.aligned.m16n8k16.row.col.f32.f16.f16.f32 "
        "{%0,%1,%2,%3}, {%4,%5,%6,%7}, {%8,%9}, {%0,%1,%2,%3};"
        : "+f"(d[0]), "+f"(d[1]), "+f"(d[2]), "+f"(d[3])
        : "r"(a0), "r"(a1), "r"(a2), "r"(a3), "r"(b0), "r"(b1));
}

// ---------------- kernel 1: Wh = h @ W -> g_WhH (fp16), E/F factors, maxes -----
#define K1_ROWS 32
#define K1T 256
#define SH 132                          // h row stride in floats
#define K1_SMEM ((INF_ * OUTF + K1_ROWS * SH) * 4)   // 49664 bytes

__global__ void __launch_bounds__(K1T, 2)
k1_proj(const float* __restrict__ h, const float* __restrict__ W,
        const float* __restrict__ a) {
    extern __shared__ float smk1[];
    float* sW = smk1;                   // [128][64]
    float* sh = smk1 + INF_ * OUTF;     // [32][SH]
    __shared__ float redA[16], redB[16];

    const int tid  = threadIdx.x;
    const int row0 = blockIdx.x * K1_ROWS;

    #pragma unroll
    for (int q = 0; q < 8; q++)         // W: 2048 float4
        ((float4*)sW)[tid + q * K1T] = ((const float4*)W)[tid + q * K1T];
    #pragma unroll
    for (int q = 0; q < 4; q++) {       // h: 1024 float4
        int slot = tid + q * K1T;
        int r = slot >> 5, cq = slot & 31;
        *(float4*)&sh[r * SH + cq * 4] =
            *(const float4*)&h[(size_t)(row0 + r) * INF_ + cq * 4];
    }
    __syncthreads();

    const int fg = tid & 15;            // 16 col groups * 4
    const int rg = tid >> 4;            // 16 row groups * 2
    const int f0 = fg * 4;
    const int r0 = rg * 2;

    float acc[2][4] = {};
    #pragma unroll 8
    for (int k = 0; k < INF_; k += 4) {
        float4 x0 = *(const float4*)&sh[r0 * SH + k];
        float4 x1 = *(const float4*)&sh[(r0 + 1) * SH + k];
        #pragma unroll
        for (int kk = 0; kk < 4; kk++) {
            float4 b = *(const float4*)&sW[(k + kk) * OUTF + f0];
            float xa = (kk == 0) ? x0.x : (kk == 1) ? x0.y : (kk == 2) ? x0.z : x0.w;
            float xb = (kk == 0) ? x1.x : (kk == 1) ? x1.y : (kk == 2) ? x1.z : x1.w;
            acc[0][0] += xa * b.x; acc[0][1] += xa * b.y;
            acc[0][2] += xa * b.z; acc[0][3] += xa * b.w;
            acc[1][0] += xb * b.x; acc[1][1] += xb * b.y;
            acc[1][2] += xb * b.z; acc[1][3] += xb * b.w;
        }
    }

    // store Wh as fp16, transposed: g_WhH[f][row], 2 rows packed per store
    #pragma unroll
    for (int cc = 0; cc < 4; cc++) {
        __half2 v = __floats2half2_rn(acc[0][cc], acc[1][cc]);
        *(__half2*)&g_WhH[(size_t)(f0 + cc) * NN + row0 + r0] = v;
    }

    // f1/f2 per row, then E/F factors
    float a1[4], a2[4];
    #pragma unroll
    for (int c = 0; c < 4; c++) { a1[c] = a[f0 + c]; a2[c] = a[OUTF + f0 + c]; }

    float locE2 = 0.f, locF2 = 0.f;
    #pragma unroll
    for (int rr = 0; rr < 2; rr++) {
        float p1 = acc[rr][0]*a1[0] + acc[rr][1]*a1[1] + acc[rr][2]*a1[2] + acc[rr][3]*a1[3];
        float p2 = acc[rr][0]*a2[0] + acc[rr][1]*a2[1] + acc[rr][2]*a2[2] + acc[rr][3]*a2[3];
        #pragma unroll
        for (int off = 8; off >= 1; off >>= 1) {
            p1 += __shfl_down_sync(0xffffffffu, p1, off, 16);
            p2 += __shfl_down_sync(0xffffffffu, p2, off, 16);
        }
        if (fg == 0) {
            int row = row0 + r0 + rr;
            float e1 = expf(p1), fl1 = expf(0.2f * p1);
            float e2 = expf(p2), fl2 = expf(0.2f * p2);
            g_E1[row] = e1;  g_F1[row] = fl1;
            g_E2[row] = e2;  g_F2[row] = fl2;
            locE2 = fmaxf(locE2, e2); locF2 = fmaxf(locF2, fl2);
        }
    }
    if (fg == 0) { redA[rg] = locE2; redB[rg] = locF2; }

    // constant rows 64..71 (ones column for denominator, zero padding)
    {
        int f = 64 + (tid >> 5);
        int r = row0 + (tid & 31);
        g_WhH[(size_t)f * NN + r] = (f == 64) ? __float2half(1.0f) : __float2half(0.0f);
    }
    __syncthreads();
    if (tid == 0) {
        float mA = 0.f, mB = 0.f;
        #pragma unroll
        for (int i = 0; i < 16; i++) { mA = fmaxf(mA, redA[i]); mB = fmaxf(mB, redB[i]); }
        atomicMax(&g_ME2i, __float_as_int(mA));
        atomicMax(&g_MF2i, __float_as_int(mB));
    }
}

// ---------------- kernel 2: fused mask+weight-gen + fp16 tensor aggregate ------
// Per CTA: 128 rows x 2048 j. 8 warps, each m16 x n72 (n-col 64 = denominator).
// j-permutation within each k16 block: lane (g,c) owns j = t*16 + 4c..4c+3;
// fragment k-slots {2c,2c+1} <-> j {4c,4c+1}; {2c+8,2c+9} <-> j {4c+2,4c+3}.
#define SBH 80                            // halves stride per B n-row (160 B; conflict-free)
#define SB_BYTES (72 * SBH * 2)           // 11520
#define SMEM_K2 (JPC * 8 + 2 * SB_BYTES)  // sE+sF (16 KB) + 2 B bufs = 39424 B

__global__ void __launch_bounds__(K2T, 2)
k2_gat(const int* __restrict__ adj) {
    extern __shared__ char smraw[];
    float* sE = (float*)smraw;                         // [JPC] E2 slice
    float* sF = (float*)(smraw + JPC * 4);             // [JPC] F2 slice
    __half* sB0 = (__half*)(smraw + JPC * 8);
    __half* sB1 = (__half*)(smraw + JPC * 8 + SB_BYTES);
    const u32 sE_a  = smem_u32(sE);
    const u32 sF_a  = smem_u32(sF);
    const u32 sB0_a = smem_u32(sB0);
    const u32 sB1_a = smem_u32(sB1);

    const int tid  = threadIdx.x;
    const int wid  = tid >> 5;
    const int lane = tid & 31;
    const int g    = lane >> 2;
    const int c    = lane & 3;
    const int rb   = blockIdx.x & 63;
    const int js   = blockIdx.x >> 6;
    const int row0 = rb * RB2;
    const int jbase = js * JPC;
    const int r0w  = row0 + wid * 16;

    // ---- group 0: sE, sF, B chunk 0 (cp.async) ----
    #pragma unroll
    for (int q = 0; q < 2; q++) {
        int i = tid + q * K2T;            // 512 float4 each
        cpa16(sE_a + i * 16, &g_E2[jbase + 4 * i]);
        cpa16(sF_a + i * 16, &g_F2[jbase + 4 * i]);
    }
    #pragma unroll
    for (int q = 0; q < 3; q++) {
        int slot = tid + q * K2T;
        if (slot < 576) {                 // 72 n-rows x 8 x 16B
            int n = slot >> 3, p = slot & 7;
            cpa16(sB0_a + n * 160 + p * 16, &g_WhH[(size_t)n * NN + jbase + p * 8]);
        }
    }
    cpa_commit();

    // ---- per-lane row factors, rescaled so weights <= 1 (softmax-invariant) ----
    const float ME2 = __int_as_float(g_ME2i);
    const float MF2 = __int_as_float(g_MF2i);
    float e1r[2], f1r[2];
    #pragma unroll
    for (int rr = 0; rr < 2; rr++) {
        int row = r0w + rr * 8 + g;
        float e1 = g_E1[row], f1 = g_F1[row];
        float inv = 1.0f / fmaxf(e1 * ME2, f1 * MF2);
        e1r[rr] = e1 * inv;
        f1r[rr] = f1 * inv;
    }
    // ---- adj pointers + depth-2 prefetch (uint4 = 4 ints per lane) ----
    const int* ap[2];
    #pragma unroll
    for (int rr = 0; rr < 2; rr++)
        ap[rr] = adj + (size_t)(r0w + rr * 8 + g) * NN + jbase + 4 * c;
    uint4 av[2][2];
    #pragma unroll
    for (int s = 0; s < 2; s++)
        #pragma unroll
        for (int rr = 0; rr < 2; rr++)
            av[s][rr] = *(const uint4*)(ap[rr] + s * 16);

    float acc[9][4];
    #pragma unroll
    for (int nt = 0; nt < 9; nt++)
        #pragma unroll
        for (int q = 0; q < 4; q++) acc[nt][q] = 0.f;

    for (int ch = 0; ch < 32; ch++) {
        const __half* sb = (ch & 1) ? sB1 : sB0;
        if (ch + 1 < 32) {               // stage next chunk into other buffer
            const u32 dsta = (ch & 1) ? sB0_a : sB1_a;
            #pragma unroll
            for (int q = 0; q < 3; q++) {
                int slot = tid + q * K2T;
                if (slot < 576) {
                    int n = slot >> 3, p = slot & 7;
                    cpa16(dsta + n * 160 + p * 16,
                          &g_WhH[(size_t)n * NN + jbase + (ch + 1) * 64 + p * 8]);
                }
            }
            cpa_commit();
            CPA_WAIT(1);                 // current chunk (and sE/sF) complete
        } else {
            CPA_WAIT(0);
        }
        __syncthreads();

        #pragma unroll
        for (int k16 = 0; k16 < 4; k16++) {
            const int t  = ch * 4 + k16;
            const int sl = t & 1;
            uint4 a0v[2];
            #pragma unroll
            for (int rr = 0; rr < 2; rr++) a0v[rr] = av[sl][rr];
            if (t + 2 < NK16) {
                #pragma unroll
                for (int rr = 0; rr < 2; rr++)
                    av[sl][rr] = *(const uint4*)(ap[rr] + (t + 2) * 16);
            }
            float4 Eq = *(const float4*)&sE[t * 16 + 4 * c];   // j = t*16+4c..4c+3
            float4 Fq = *(const float4*)&sF[t * 16 + 4 * c];
            u32 A0[2], A2[2];
            #pragma unroll
            for (int rr = 0; rr < 2; rr++) {
                float w0 = fmaxf(e1r[rr] * Eq.x, f1r[rr] * Fq.x);
                float w1 = fmaxf(e1r[rr] * Eq.y, f1r[rr] * Fq.y);
                float w2 = fmaxf(e1r[rr] * Eq.z, f1r[rr] * Fq.z);
                float w3 = fmaxf(e1r[rr] * Eq.w, f1r[rr] * Fq.w);
                A0[rr] = packh2(w1, w0) & pairmask2(a0v[rr].x, a0v[rr].y);
                A2[rr] = packh2(w3, w2) & pairmask2(a0v[rr].z, a0v[rr].w);
            }
            #pragma unroll
            for (int nt = 0; nt < 9; nt++) {
                uint2 b = *(const uint2*)&sb[(nt * 8 + g) * SBH + k16 * 16 + 4 * c];
                mma_f16(acc[nt], A0[0], A0[1], A2[0], A2[1], b.x, b.y);
            }
        }
        __syncthreads();                 // buffer consumed; next iter may overwrite
    }

    // ---- epilogue: write partials (row scaling cancels in num/den) ----
    {
        int ra = r0w + g;
        int rc = r0w + 8 + g;
        #pragma unroll
        for (int nt = 0; nt < 8; nt++) {
            int col = nt * 8 + 2 * c;
            *(float2*)&g_part[((size_t)js * NN + ra) * OUTF + col] =
                make_float2(acc[nt][0], acc[nt][1]);
            *(float2*)&g_part[((size_t)js * NN + rc) * OUTF + col] =
                make_float2(acc[nt][2], acc[nt][3]);
        }
        if (c == 0) {                    // n-col 64 (ones) = denominator
            g_denp[js * NN + ra] = acc[8][0];
            g_denp[js * NN + rc] = acc[8][2];
        }
    }
}

// ---------------- kernel 3: reduce partials, normalize, elu --------------------
__global__ void __launch_bounds__(256)
k3_final(float* __restrict__ out) {
    int idx = blockIdx.x * 256 + threadIdx.x;   // 0 .. NN*OUTF-1
    int row = idx >> 6;
    float num = 0.f, den = 0.f;
    #pragma unroll
    for (int s = 0; s < JSPLIT; s++) {
        num += g_part[(size_t)s * NN * OUTF + idx];
        den += g_denp[s * NN + row];
    }
    float v = num / den;
    out[idx] = (v > 0.f) ? v : expm1f(v);
}

// ---------------- launcher -----------------------------------------------------
extern "C" void kernel_launch(void* const* d_in, const int* in_sizes, int n_in,
                              void* d_out, int out_size) {
    const float* h = nullptr; const int* adj = nullptr;
    const float* W = nullptr; const float* a = nullptr;
    for (int i = 0; i < n_in; i++) {
        switch (in_sizes[i]) {
            case 1048576:  h   = (const float*)d_in[i]; break;
            case 67108864: adj = (const int*)  d_in[i]; break;
            case 8192:     W   = (const float*)d_in[i]; break;
            case 128:      a   = (const float*)d_in[i]; break;
            default: break;
        }
    }
    float* out = (float*)d_out;

    cudaFuncSetAttribute(k1_proj, cudaFuncAttributeMaxDynamicSharedMemorySize, K1_SMEM);

    k1_proj<<<NN / K1_ROWS, K1T, K1_SMEM>>>(h, W, a);
    k2_gat<<<64 * JSPLIT, K2T, SMEM_K2>>>(adj);
    k3_final<<<(NN * OUTF) / 256, 256>>>(out);
    (void)out_size;
}

// round 9
// speedup vs baseline: 10.0079x; 1.0869x over previous
#include <cuda_runtime.h>
#include <cuda_fp16.h>
#include <math.h>
#include <stdint.h>

#define NN 8192
#define INF_ 128
#define OUTF 64

typedef unsigned int u32;

#define JSPLIT 4
#define JPC (NN / JSPLIT)        // 2048 j per CTA
#define RB2 128                  // rows per k2 CTA
#define NK16 (JPC / 16)          // 128 k16-steps
#define K2T 256

// ---------------- scratch (__device__ globals; no allocation) ------------------
__device__ __half g_WhH[72 * NN];           // [n][j] fp16; 0..63 = WhT, 64 = ones, 65..71 = 0
__device__ float g_E1[NN], g_F1[NN];        // exp(f1), exp(0.2 f1)   (unscaled)
__device__ float g_E2[NN], g_F2[NN];        // exp(f2), exp(0.2 f2)
__device__ int   g_ME2i, g_MF2i;            // global max of E2 / F2 (float bits, positive)
__device__ float g_part[JSPLIT * NN * OUTF];// numerator partials
__device__ float g_denp[JSPLIT * NN];       // denominator partials

// ---------------- helpers -------------------------------------------------------
__device__ __forceinline__ u32 packh2(float hi, float lo) {
    u32 d; asm("cvt.rn.f16x2.f32 %0, %1, %2;" : "=r"(d) : "f"(hi), "f"(lo));
    return d;
}
__device__ __forceinline__ u32 pairmask2(u32 ax, u32 ay) {   // adj in {0,1}
    return ((u32)(-(int)ax) & 0xFFFFu) | ((u32)(-(int)ay) << 16);
}
__device__ __forceinline__ u32 smem_u32(const void* p) {
    u32 a;
    asm("{ .reg .u64 t; cvta.to.shared.u64 t, %1; cvt.u32.u64 %0, t; }" : "=r"(a) : "l"(p));
    return a;
}
__device__ __forceinline__ void cpa16(u32 dst, const void* src) {
    asm volatile("cp.async.cg.shared.global [%0], [%1], 16;" :: "r"(dst), "l"(src));
}
__device__ __forceinline__ void cpa_commit() {
    asm volatile("cp.async.commit_group;" ::: "memory");
}
#define CPA_WAIT(n) asm volatile("cp.async.wait_group %0;" :: "n"(n) : "memory")

// m16n8k16 fp16 MMA (row.col), f32 accum.
__device__ __forceinline__ void mma_f16(float* d, u32 a0, u32 a1, u32 a2, u32 a3,
                                        u32 b0, u32 b1) {
    asm volatile(
        "mma.sync.aligned.m16n8k16.row.col.f32.f16.f16.f32 "
        "{%0,%1,%2,%3}, {%4,%5,%6,%7}, {%8,%9}, {%0,%1,%2,%3};"
        : "+f"(d[0]), "+f"(d[1]), "+f"(d[2]), "+f"(d[3])
        : "r"(a0), "r"(a1), "r"(a2), "r"(a3), "r"(b0), "r"(b1));
}

// ---------------- kernel 1: Wh = h @ W -> g_WhH (fp16), E/F factors, maxes -----
#define K1_ROWS 16
#define K1T 128
#define SH 132                          // h row stride in floats
#define K1_SMEM ((INF_ * OUTF + K1_ROWS * SH) * 4)   // 41216 bytes

__global__ void __launch_bounds__(K1T, 5)
k1_proj(const float* __restrict__ h, const float* __restrict__ W,
        const float* __restrict__ a) {
    extern __shared__ float smk1[];
    float* sW = smk1;                   // [128][64]
    float* sh = smk1 + INF_ * OUTF;     // [16][SH]
    __shared__ float redA[8], redB[8];

    const int tid  = threadIdx.x;
    const int row0 = blockIdx.x * K1_ROWS;

    #pragma unroll
    for (int q = 0; q < 16; q++)        // W: 2048 float4
        ((float4*)sW)[tid + q * K1T] = ((const float4*)W)[tid + q * K1T];
    #pragma unroll
    for (int q = 0; q < 4; q++) {       // h: 512 float4
        int slot = tid + q * K1T;
        int r = slot >> 5, cq = slot & 31;
        *(float4*)&sh[r * SH + cq * 4] =
            *(const float4*)&h[(size_t)(row0 + r) * INF_ + cq * 4];
    }
    __syncthreads();

    const int fg = tid & 15;            // 16 col groups * 4
    const int rg = tid >> 4;            // 8 row groups * 2
    const int f0 = fg * 4;
    const int r0 = rg * 2;

    float acc[2][4] = {};
    #pragma unroll 8
    for (int k = 0; k < INF_; k += 4) {
        float4 x0 = *(const float4*)&sh[r0 * SH + k];
        float4 x1 = *(const float4*)&sh[(r0 + 1) * SH + k];
        #pragma unroll
        for (int kk = 0; kk < 4; kk++) {
            float4 b = *(const float4*)&sW[(k + kk) * OUTF + f0];
            float xa = (kk == 0) ? x0.x : (kk == 1) ? x0.y : (kk == 2) ? x0.z : x0.w;
            float xb = (kk == 0) ? x1.x : (kk == 1) ? x1.y : (kk == 2) ? x1.z : x1.w;
            acc[0][0] += xa * b.x; acc[0][1] += xa * b.y;
            acc[0][2] += xa * b.z; acc[0][3] += xa * b.w;
            acc[1][0] += xb * b.x; acc[1][1] += xb * b.y;
            acc[1][2] += xb * b.z; acc[1][3] += xb * b.w;
        }
    }

    // store Wh as fp16, transposed: g_WhH[f][row], 2 rows packed per store
    #pragma unroll
    for (int cc = 0; cc < 4; cc++) {
        __half2 v = __floats2half2_rn(acc[0][cc], acc[1][cc]);
        *(__half2*)&g_WhH[(size_t)(f0 + cc) * NN + row0 + r0] = v;
    }

    // f1/f2 per row, then E/F factors
    float a1[4], a2[4];
    #pragma unroll
    for (int c = 0; c < 4; c++) { a1[c] = a[f0 + c]; a2[c] = a[OUTF + f0 + c]; }

    float locE2 = 0.f, locF2 = 0.f;
    #pragma unroll
    for (int rr = 0; rr < 2; rr++) {
        float p1 = acc[rr][0]*a1[0] + acc[rr][1]*a1[1] + acc[rr][2]*a1[2] + acc[rr][3]*a1[3];
        float p2 = acc[rr][0]*a2[0] + acc[rr][1]*a2[1] + acc[rr][2]*a2[2] + acc[rr][3]*a2[3];
        #pragma unroll
        for (int off = 8; off >= 1; off >>= 1) {
            p1 += __shfl_down_sync(0xffffffffu, p1, off, 16);
            p2 += __shfl_down_sync(0xffffffffu, p2, off, 16);
        }
        if (fg == 0) {
            int row = row0 + r0 + rr;
            float e1 = expf(p1), fl1 = expf(0.2f * p1);
            float e2 = expf(p2), fl2 = expf(0.2f * p2);
            g_E1[row] = e1;  g_F1[row] = fl1;
            g_E2[row] = e2;  g_F2[row] = fl2;
            locE2 = fmaxf(locE2, e2); locF2 = fmaxf(locF2, fl2);
        }
    }
    if (fg == 0) { redA[rg] = locE2; redB[rg] = locF2; }

    // constant rows 64..71 (ones column for denominator, zero padding)
    {
        int f = 64 + (tid >> 4);
        int r = row0 + (tid & 15);
        g_WhH[(size_t)f * NN + r] = (f == 64) ? __float2half(1.0f) : __float2half(0.0f);
    }
    __syncthreads();
    if (tid == 0) {
        float mA = 0.f, mB = 0.f;
        #pragma unroll
        for (int i = 0; i < 8; i++) { mA = fmaxf(mA, redA[i]); mB = fmaxf(mB, redB[i]); }
        atomicMax(&g_ME2i, __float_as_int(mA));
        atomicMax(&g_MF2i, __float_as_int(mB));
    }
}

// ---------------- kernel 2: fused mask+weight-gen + fp16 tensor aggregate ------
// Per CTA: 128 rows x 2048 j. 8 warps, each m16 x n72 (n-col 64 = denominator).
// j-permutation within each k16 block: lane (g,c) owns j = t*16 + 4c..4c+3.
// Single-sync double-buffered cp.async pipeline; adj prefetch depth 4.
#define SBH 80                            // halves stride per B n-row (160 B)
#define SB_BYTES (72 * SBH * 2)           // 11520
#define SMEM_K2 (JPC * 8 + 2 * SB_BYTES)  // sE+sF (16 KB) + 2 B bufs = 39424 B

__global__ void __launch_bounds__(K2T, 2)
k2_gat(const int* __restrict__ adj) {
    extern __shared__ char smraw[];
    float* sE = (float*)smraw;                         // [JPC] E2 slice
    float* sF = (float*)(smraw + JPC * 4);             // [JPC] F2 slice
    __half* sB0 = (__half*)(smraw + JPC * 8);
    __half* sB1 = (__half*)(smraw + JPC * 8 + SB_BYTES);
    const u32 sE_a  = smem_u32(sE);
    const u32 sF_a  = smem_u32(sF);
    const u32 sB0_a = smem_u32(sB0);
    const u32 sB1_a = smem_u32(sB1);

    const int tid  = threadIdx.x;
    const int wid  = tid >> 5;
    const int lane = tid & 31;
    const int g    = lane >> 2;
    const int c    = lane & 3;
    const int rb   = blockIdx.x & 63;
    const int js   = blockIdx.x >> 6;
    const int row0 = rb * RB2;
    const int jbase = js * JPC;
    const int r0w  = row0 + wid * 16;

    // ---- group 0: sE, sF, B chunk 0 (cp.async) ----
    #pragma unroll
    for (int q = 0; q < 2; q++) {
        int i = tid + q * K2T;            // 512 float4 each
        cpa16(sE_a + i * 16, &g_E2[jbase + 4 * i]);
        cpa16(sF_a + i * 16, &g_F2[jbase + 4 * i]);
    }
    #pragma unroll
    for (int q = 0; q < 3; q++) {
        int slot = tid + q * K2T;
        if (slot < 576) {                 // 72 n-rows x 8 x 16B
            int n = slot >> 3, p = slot & 7;
            cpa16(sB0_a + n * 160 + p * 16, &g_WhH[(size_t)n * NN + jbase + p * 8]);
        }
    }
    cpa_commit();

    // ---- per-lane row factors, rescaled so weights <= 1 (softmax-invariant) ----
    const float ME2 = __int_as_float(g_ME2i);
    const float MF2 = __int_as_float(g_MF2i);
    float e1r[2], f1r[2];
    #pragma unroll
    for (int rr = 0; rr < 2; rr++) {
        int row = r0w + rr * 8 + g;
        float e1 = g_E1[row], f1 = g_F1[row];
        float inv = 1.0f / fmaxf(e1 * ME2, f1 * MF2);
        e1r[rr] = e1 * inv;
        f1r[rr] = f1 * inv;
    }
    // ---- adj pointers + depth-4 prefetch (uint4 = 4 ints per lane) ----
    const int* ap[2];
    #pragma unroll
    for (int rr = 0; rr < 2; rr++)
        ap[rr] = adj + (size_t)(r0w + rr * 8 + g) * NN + jbase + 4 * c;
    uint4 av[4][2];
    #pragma unroll
    for (int s = 0; s < 4; s++)
        #pragma unroll
        for (int rr = 0; rr < 2; rr++)
            av[s][rr] = *(const uint4*)(ap[rr] + s * 16);

    float acc[9][4];
    #pragma unroll
    for (int nt = 0; nt < 9; nt++)
        #pragma unroll
        for (int q = 0; q < 4; q++) acc[nt][q] = 0.f;

    for (int ch = 0; ch < 32; ch++) {
        const __half* sb = (ch & 1) ? sB1 : sB0;
        CPA_WAIT(0);                      // buf ch ready (incl. sE/sF at ch=0)
        __syncthreads();
        if (ch + 1 < 32) {                // stage next chunk AFTER the sync:
            const u32 dsta = (ch & 1) ? sB0_a : sB1_a;   // readers of this buf
            #pragma unroll                                // finished pre-sync
            for (int q = 0; q < 3; q++) {
                int slot = tid + q * K2T;
                if (slot < 576) {
                    int n = slot >> 3, p = slot & 7;
                    cpa16(dsta + n * 160 + p * 16,
                          &g_WhH[(size_t)n * NN + jbase + (ch + 1) * 64 + p * 8]);
                }
            }
            cpa_commit();
        }

        #pragma unroll
        for (int k16 = 0; k16 < 4; k16++) {
            const int t  = ch * 4 + k16;
            const int sl = t & 3;
            uint4 a0v[2];
            #pragma unroll
            for (int rr = 0; rr < 2; rr++) a0v[rr] = av[sl][rr];
            if (t + 4 < NK16) {
                #pragma unroll
                for (int rr = 0; rr < 2; rr++)
                    av[sl][rr] = *(const uint4*)(ap[rr] + (t + 4) * 16);
            }
            float4 Eq = *(const float4*)&sE[t * 16 + 4 * c];   // j = t*16+4c..4c+3
            float4 Fq = *(const float4*)&sF[t * 16 + 4 * c];
            u32 A0[2], A2[2];
            #pragma unroll
            for (int rr = 0; rr < 2; rr++) {
                float w0 = fmaxf(e1r[rr] * Eq.x, f1r[rr] * Fq.x);
                float w1 = fmaxf(e1r[rr] * Eq.y, f1r[rr] * Fq.y);
                float w2 = fmaxf(e1r[rr] * Eq.z, f1r[rr] * Fq.z);
                float w3 = fmaxf(e1r[rr] * Eq.w, f1r[rr] * Fq.w);
                A0[rr] = packh2(w1, w0) & pairmask2(a0v[rr].x, a0v[rr].y);
                A2[rr] = packh2(w3, w2) & pairmask2(a0v[rr].z, a0v[rr].w);
            }
            #pragma unroll
            for (int nt = 0; nt < 9; nt++) {
                uint2 b = *(const uint2*)&sb[(nt * 8 + g) * SBH + k16 * 16 + 4 * c];
                mma_f16(acc[nt], A0[0], A0[1], A2[0], A2[1], b.x, b.y);
            }
        }
    }

    // ---- epilogue: write partials (row scaling cancels in num/den) ----
    {
        int ra = r0w + g;
        int rc = r0w + 8 + g;
        #pragma unroll
        for (int nt = 0; nt < 8; nt++) {
            int col = nt * 8 + 2 * c;
            *(float2*)&g_part[((size_t)js * NN + ra) * OUTF + col] =
                make_float2(acc[nt][0], acc[nt][1]);
            *(float2*)&g_part[((size_t)js * NN + rc) * OUTF + col] =
                make_float2(acc[nt][2], acc[nt][3]);
        }
        if (c == 0) {                    // n-col 64 (ones) = denominator
            g_denp[js * NN + ra] = acc[8][0];
            g_denp[js * NN + rc] = acc[8][2];
        }
    }
}

// ---------------- kernel 3: reduce partials, normalize, elu (vectorized) -------
__global__ void __launch_bounds__(256)
k3_final(float* __restrict__ out) {
    int q   = blockIdx.x * 256 + threadIdx.x;   // float4 index
    int idx = q * 4;
    int row = idx >> 6;
    float4 num = make_float4(0.f, 0.f, 0.f, 0.f);
    float den = 0.f;
    #pragma unroll
    for (int s = 0; s < JSPLIT; s++) {
        float4 p = *(const float4*)&g_part[(size_t)s * NN * OUTF + idx];
        num.x += p.x; num.y += p.y; num.z += p.z; num.w += p.w;
        den += g_denp[s * NN + row];
    }
    float inv = 1.f / den;
    float v0 = num.x * inv, v1 = num.y * inv, v2 = num.z * inv, v3 = num.w * inv;
    v0 = (v0 > 0.f) ? v0 : expm1f(v0);
    v1 = (v1 > 0.f) ? v1 : expm1f(v1);
    v2 = (v2 > 0.f) ? v2 : expm1f(v2);
    v3 = (v3 > 0.f) ? v3 : expm1f(v3);
    *(float4*)&out[idx] = make_float4(v0, v1, v2, v3);
}

// ---------------- launcher -----------------------------------------------------
extern "C" void kernel_launch(void* const* d_in, const int* in_sizes, int n_in,
                              void* d_out, int out_size) {
    const float* h = nullptr; const int* adj = nullptr;
    const float* W = nullptr; const float* a = nullptr;
    for (int i = 0; i < n_in; i++) {
        switch (in_sizes[i]) {
            case 1048576:  h   = (const float*)d_in[i]; break;
            case 67108864: adj = (const int*)  d_in[i]; break;
            case 8192:     W   = (const float*)d_in[i]; break;
            case 128:      a   = (const float*)d_in[i]; break;
            default: break;
        }
    }
    float* out = (float*)d_out;

    cudaFuncSetAttribute(k1_proj, cudaFuncAttributeMaxDynamicSharedMemorySize, K1_SMEM);

    k1_proj<<<NN / K1_ROWS, K1T, K1_SMEM>>>(h, W, a);
    k2_gat<<<64 * JSPLIT, K2T, SMEM_K2>>>(adj);
    k3_final<<<(NN * OUTF) / 1024, 256>>>(out);
    (void)out_size;
}